// round 1
// baseline (speedup 1.0000x reference)
#include <cuda_runtime.h>
#include <cstdint>

// Problem constants
#define BB    8192
#define NVV   778
#define NJJ   16
#define KTOT  145            // 10 shape + 135 pose
#define CTOT  2334           // NV*3
#define CPAD  2496           // 13 * 192
#define CTILE 192
#define BTILE 32
#define VTILE 64

// Scratch (device globals; no dynamic allocation allowed)
__device__ __align__(16) float g_D[KTOT * CPAD];      // combined dirs, padded
__device__ __align__(16) float g_bias[CPAD];          // verts_template flat, padded
__device__ __align__(16) float g_J0[NJJ * 3];
__device__ __align__(16) float g_JS[NJJ * 3 * 10];
__device__ __align__(16) float g_M[BB * NJJ * 12];    // M'' = g @ [R|t_corr], +trans folded

__constant__ int c_par[16] = {0,0,1,2,0,4,5,0,7,8,0,10,11,0,13,14};
// inverse of ORDER for joints 0..15 (output position of joint j)
__constant__ int c_inv[16] = {0,5,6,7,9,10,11,17,18,19,13,14,15,1,2,3};

// ---------------------------------------------------------------------------
// K0: build combined direction matrix D (145 x 2496, zero-padded) and bias
// ---------------------------------------------------------------------------
__global__ void k0_build(const float* __restrict__ vt,
                         const float* __restrict__ sd,
                         const float* __restrict__ pd) {
    int idx = blockIdx.x * blockDim.x + threadIdx.x;
    if (idx < KTOT * CPAD) {
        int k = idx / CPAD;
        int c = idx - k * CPAD;
        float v = 0.f;
        if (c < CTOT) v = (k < 10) ? sd[c * 10 + k] : pd[(k - 10) * CTOT + c];
        g_D[idx] = v;
    }
    if (idx < CPAD) g_bias[idx] = (idx < CTOT) ? vt[idx] : 0.f;
}

// ---------------------------------------------------------------------------
// K1: J0[j,k] = sum_v Jreg[j,v]*vt[v,k];  JS[j,k,l] = sum_v Jreg[j,v]*sd[v,k,l]
// ---------------------------------------------------------------------------
__global__ void k1_jreg(const float* __restrict__ jreg,
                        const float* __restrict__ vt,
                        const float* __restrict__ sd) {
    __shared__ float red[33 * 128];
    const int j = blockIdx.x, tid = threadIdx.x;
    float acc[33];
#pragma unroll
    for (int o = 0; o < 33; o++) acc[o] = 0.f;
    for (int v = tid; v < NVV; v += 128) {
        float w = jreg[j * NVV + v];
#pragma unroll
        for (int k = 0; k < 3; k++) {
            acc[k] += w * vt[v * 3 + k];
#pragma unroll
            for (int l = 0; l < 10; l++)
                acc[3 + k * 10 + l] += w * sd[(v * 3 + k) * 10 + l];
        }
    }
    for (int o = 0; o < 33; o++) red[o * 128 + tid] = acc[o];
    __syncthreads();
    if (tid < 33) {
        float s = 0.f;
        for (int i = 0; i < 128; i++) s += red[tid * 128 + i];
        if (tid < 3) g_J0[j * 3 + tid] = s;
        else {
            int o = tid - 3;
            int k = o / 10, l = o - k * 10;
            g_JS[(j * 3 + k) * 10 + l] = s;
        }
    }
}

// ---------------------------------------------------------------------------
// K2: per-batch joint chain, M'' matrices, and the 16 regular joints
// ---------------------------------------------------------------------------
__device__ __forceinline__ void mul4(const float* a, float* d) {
    float t[16];
#pragma unroll
    for (int r = 0; r < 4; r++)
#pragma unroll
        for (int c = 0; c < 4; c++)
            t[r * 4 + c] = a[r * 4 + 0] * d[0 + c] + a[r * 4 + 1] * d[4 + c] +
                           a[r * 4 + 2] * d[8 + c] + a[r * 4 + 3] * d[12 + c];
#pragma unroll
    for (int i = 0; i < 16; i++) d[i] = t[i];
}

__global__ void k2_joints(const float* __restrict__ grmt,
                          const float* __restrict__ frmt,
                          const float* __restrict__ shape,
                          const float* __restrict__ trans,
                          float* __restrict__ outJ) {
    __shared__ float sJ[16][3];
    __shared__ float sM[16][16];
    __shared__ float sg[9], st[3], ssh[10];
    const int b = blockIdx.x, tid = threadIdx.x;

    if (tid < 9)  sg[tid]  = grmt[b * 9 + tid];
    if (tid < 3)  st[tid]  = trans[b * 3 + tid];
    if (tid < 10) ssh[tid] = shape[b * 10 + tid];
    __syncthreads();

    if (tid < 48) {
        int j = tid / 3, k = tid - j * 3;
        float a = g_J0[j * 3 + k];
#pragma unroll
        for (int l = 0; l < 10; l++) a += ssh[l] * g_JS[(j * 3 + k) * 10 + l];
        sJ[j][k] = a;
    }
    __syncthreads();

    if (tid < 16) {
        int j = tid;
        float R[9];
        if (j == 0) {
            R[0]=1;R[1]=0;R[2]=0;R[3]=0;R[4]=1;R[5]=0;R[6]=0;R[7]=0;R[8]=1;
        } else {
#pragma unroll
            for (int i = 0; i < 9; i++) R[i] = frmt[b * 135 + (j - 1) * 9 + i];
        }
        float t0 = sJ[j][0], t1 = sJ[j][1], t2 = sJ[j][2];
        if (j > 0) {
            int p = c_par[j];
            t0 -= sJ[p][0]; t1 -= sJ[p][1]; t2 -= sJ[p][2];
        }
        float* m = sM[j];
        m[0]=R[0]; m[1]=R[1]; m[2]=R[2];  m[3]=t0;
        m[4]=R[3]; m[5]=R[4]; m[6]=R[5];  m[7]=t1;
        m[8]=R[6]; m[9]=R[7]; m[10]=R[8]; m[11]=t2;
        m[12]=0.f; m[13]=0.f; m[14]=0.f;  m[15]=1.f;
    }
    __syncthreads();

    if (tid < 5) {
        int j = 1 + 3 * tid;
        mul4(sM[0], sM[j]);
        mul4(sM[j], sM[j + 1]);
        mul4(sM[j + 1], sM[j + 2]);
    }
    __syncthreads();

    if (tid < 16) {
        int j = tid;
        const float* m = sM[j];
        float jt0 = m[3], jt1 = m[7], jt2 = m[11];
        float J0 = sJ[j][0], J1 = sJ[j][1], J2 = sJ[j][2];
        float tc0 = jt0 - (m[0] * J0 + m[1] * J1 + m[2]  * J2);
        float tc1 = jt1 - (m[4] * J0 + m[5] * J1 + m[6]  * J2);
        float tc2 = jt2 - (m[8] * J0 + m[9] * J1 + m[10] * J2);
        float* o = &g_M[(b * 16 + j) * 12];
        int jp = c_inv[j];
#pragma unroll
        for (int r = 0; r < 3; r++) {
            float a = sg[r * 3 + 0], bb = sg[r * 3 + 1], cc = sg[r * 3 + 2];
            o[r * 4 + 0] = a * m[0] + bb * m[4] + cc * m[8];
            o[r * 4 + 1] = a * m[1] + bb * m[5] + cc * m[9];
            o[r * 4 + 2] = a * m[2] + bb * m[6] + cc * m[10];
            o[r * 4 + 3] = a * tc0  + bb * tc1  + cc * tc2 + st[r];
            outJ[(b * 21 + jp) * 3 + r] = a * jt0 + bb * jt1 + cc * jt2 + st[r];
        }
    }
}

// ---------------------------------------------------------------------------
// K3: fused pose-blend GEMM + LBS blend + transform + writeout
//   block = 256 threads, tile = 32 batch x 192 cols (64 vertices)
// ---------------------------------------------------------------------------
__global__ __launch_bounds__(256) void k3_main(const float* __restrict__ shape,
                                               const float* __restrict__ finger,
                                               const float* __restrict__ lbs,
                                               float* __restrict__ outV,
                                               float* __restrict__ outJ) {
    extern __shared__ __align__(16) float SM[];   // 14144 floats = 56,576 B
    const int tid = threadIdx.x;
    const int b0 = blockIdx.x * BTILE;
    const int c0 = blockIdx.y * CTILE;
    const int v0 = blockIdx.y * VTILE;

    float* sFeat = SM;               // 32 x 148
    float* sD    = SM + 32 * 148;    // up to 49 x 192

    // ---- load feat tile: [shape | finger_rmt - I] ----
    for (int idx = tid; idx < BTILE * KTOT; idx += 256) {
        int r = idx / KTOT, k = idx - r * KTOT;
        float val;
        if (k < 10) val = shape[(b0 + r) * 10 + k];
        else {
            int q = k - 10;
            val = finger[(b0 + r) * 135 + q];
            if (((q % 9) & 3) == 0) val -= 1.0f;   // diag positions 0,4,8
        }
        sFeat[r * 148 + k] = val;
    }

    float acc[4][6];
#pragma unroll
    for (int i = 0; i < 4; i++)
#pragma unroll
        for (int j = 0; j < 6; j++) acc[i][j] = 0.f;

    const int bg = tid >> 5;       // batch group 0..7 (4 rows each)
    const int lane = tid & 31;     // column group (cols lane + 32*j)

    for (int kc = 0; kc < KTOT; kc += 49) {
        const int KC = min(49, KTOT - kc);
        __syncthreads();
        for (int idx = tid; idx < KC * 48; idx += 256) {
            int k = idx / 48, c4 = idx - k * 48;
            reinterpret_cast<float4*>(sD)[k * 48 + c4] =
                *reinterpret_cast<const float4*>(&g_D[(kc + k) * CPAD + c0 + c4 * 4]);
        }
        __syncthreads();
        for (int k = 0; k < KC; ++k) {
            const float* fr = &sFeat[bg * 4 * 148 + kc + k];
            float f0 = fr[0], f1 = fr[148], f2 = fr[296], f3 = fr[444];
            const float* dr = &sD[k * CTILE + lane];
#pragma unroll
            for (int j = 0; j < 6; ++j) {
                float d = dr[32 * j];
                acc[0][j] = fmaf(f0, d, acc[0][j]);
                acc[1][j] = fmaf(f1, d, acc[1][j]);
                acc[2][j] = fmaf(f2, d, acc[2][j]);
                acc[3][j] = fmaf(f3, d, acc[3][j]);
            }
        }
    }
    __syncthreads();

    // ---- stage V into smem, load M'' tile and weights ----
    float* sV  = SM;                 // 32 x 192
    float* sMm = SM + 6144;          // 32 x 192 (16 joints x 12)
    float* sW  = SM + 12288;         // 64 x 17 (padded)

#pragma unroll
    for (int i = 0; i < 4; i++)
#pragma unroll
        for (int j = 0; j < 6; j++) {
            int c = lane + 32 * j;
            sV[(bg * 4 + i) * CTILE + c] = acc[i][j] + g_bias[c0 + c];
        }
    for (int idx = tid; idx < 1536; idx += 256)
        reinterpret_cast<float4*>(sMm)[idx] =
            *reinterpret_cast<const float4*>(&g_M[b0 * 192 + idx * 4]);
    for (int idx = tid; idx < VTILE * 16; idx += 256) {
        int vl = idx >> 4, j = idx & 15;
        sW[vl * 17 + j] = (v0 + vl < NVV) ? lbs[(v0 + vl) * 16 + j] : 0.f;
    }
    __syncthreads();

    // ---- epilogue: each thread handles 2 batches x 4 vertices ----
    const int vq = tid & 15;   // vertex group (4 verts)
    const int bq = tid >> 4;   // batch group (2 rows)

    float X[8], Yv[8], Z[8];
#pragma unroll
    for (int bi = 0; bi < 2; bi++)
#pragma unroll
        for (int vi = 0; vi < 4; vi++) {
            const float* p = &sV[(bq * 2 + bi) * CTILE + (vq * 4 + vi) * 3];
            X[bi * 4 + vi] = p[0]; Yv[bi * 4 + vi] = p[1]; Z[bi * 4 + vi] = p[2];
        }

    float o[24];
#pragma unroll
    for (int i = 0; i < 24; i++) o[i] = 0.f;

#pragma unroll 4
    for (int j = 0; j < 16; j++) {
        float w[4];
#pragma unroll
        for (int vi = 0; vi < 4; vi++) w[vi] = sW[(vq * 4 + vi) * 17 + j];
#pragma unroll
        for (int bi = 0; bi < 2; bi++) {
            const float* m = &sMm[(bq * 2 + bi) * CTILE + j * 12];
            float m0 = m[0], m1 = m[1], m2 = m[2],  m3 = m[3];
            float m4 = m[4], m5 = m[5], m6 = m[6],  m7 = m[7];
            float m8 = m[8], m9 = m[9], m10 = m[10], m11 = m[11];
#pragma unroll
            for (int vi = 0; vi < 4; vi++) {
                float x = X[bi * 4 + vi], y = Yv[bi * 4 + vi], z = Z[bi * 4 + vi];
                float t0 = fmaf(m0, x, fmaf(m1, y, fmaf(m2,  z, m3)));
                float t1 = fmaf(m4, x, fmaf(m5, y, fmaf(m6,  z, m7)));
                float t2 = fmaf(m8, x, fmaf(m9, y, fmaf(m10, z, m11)));
                int base = (bi * 4 + vi) * 3;
                o[base + 0] = fmaf(w[vi], t0, o[base + 0]);
                o[base + 1] = fmaf(w[vi], t1, o[base + 1]);
                o[base + 2] = fmaf(w[vi], t2, o[base + 2]);
            }
        }
    }

    // ---- fingertip joints ----
#pragma unroll
    for (int bi = 0; bi < 2; bi++)
#pragma unroll
        for (int vi = 0; vi < 4; vi++) {
            int v = v0 + vq * 4 + vi;
            int tp = -1;
            if (v == 745) tp = 4; else if (v == 317) tp = 8;
            else if (v == 444) tp = 12; else if (v == 556) tp = 16;
            else if (v == 673) tp = 20;
            if (tp >= 0) {
                int b = b0 + bq * 2 + bi;
                int base = (bi * 4 + vi) * 3;
                outJ[(b * 21 + tp) * 3 + 0] = o[base + 0];
                outJ[(b * 21 + tp) * 3 + 1] = o[base + 1];
                outJ[(b * 21 + tp) * 3 + 2] = o[base + 2];
            }
        }

    __syncthreads();   // all X/Y/Z reads done before overwriting sV
#pragma unroll
    for (int bi = 0; bi < 2; bi++)
#pragma unroll
        for (int vi = 0; vi < 4; vi++) {
            float* p = &sV[(bq * 2 + bi) * CTILE + (vq * 4 + vi) * 3];
            int base = (bi * 4 + vi) * 3;
            p[0] = o[base + 0]; p[1] = o[base + 1]; p[2] = o[base + 2];
        }
    __syncthreads();

    // ---- coalesced writeout ----
    const int cvalid = min(CTILE, (NVV - v0) * 3);
    if (cvalid == CTILE) {
        for (int idx = tid; idx < BTILE * 96; idx += 256) {
            int bl = idx / 96, c2 = idx - bl * 96;
            *reinterpret_cast<float2*>(&outV[(size_t)(b0 + bl) * CTOT + v0 * 3 + c2 * 2]) =
                *reinterpret_cast<const float2*>(&sV[bl * CTILE + c2 * 2]);
        }
    } else {
        for (int idx = tid; idx < BTILE * cvalid; idx += 256) {
            int bl = idx / cvalid, c = idx - bl * cvalid;
            outV[(size_t)(b0 + bl) * CTOT + v0 * 3 + c] = sV[bl * CTILE + c];
        }
    }
}

// ---------------------------------------------------------------------------
extern "C" void kernel_launch(void* const* d_in, const int* in_sizes, int n_in,
                              void* d_out, int out_size) {
    const float* grmt  = (const float*)d_in[0];  // (B,1,3,3)
    const float* frmt  = (const float*)d_in[1];  // (B,15,3,3)
    const float* shape = (const float*)d_in[2];  // (B,10)
    const float* trans = (const float*)d_in[3];  // (B,3)
    const float* vt    = (const float*)d_in[4];  // (NV,3)
    const float* sd    = (const float*)d_in[5];  // (NV,3,10)
    const float* jreg  = (const float*)d_in[6];  // (16,NV)
    const float* pd    = (const float*)d_in[7];  // (135, NV*3)
    const float* lbs   = (const float*)d_in[8];  // (NV,16)

    float* out  = (float*)d_out;
    float* outV = out;
    float* outJ = out + (size_t)BB * CTOT;

    static bool attr_done = false;
    if (!attr_done) {
        cudaFuncSetAttribute(k3_main, cudaFuncAttributeMaxDynamicSharedMemorySize,
                             14144 * sizeof(float));
        attr_done = true;
    }

    k0_build<<<(KTOT * CPAD + 255) / 256, 256>>>(vt, sd, pd);
    k1_jreg<<<NJJ, 128>>>(jreg, vt, sd);
    k2_joints<<<BB, 64>>>(grmt, frmt, shape, trans, outJ);
    k3_main<<<dim3(BB / BTILE, 13), 256, 14144 * sizeof(float)>>>(shape, frmt, lbs, outV, outJ);
}

// round 3
// speedup vs baseline: 1.2446x; 1.2446x over previous
#include <cuda_runtime.h>
#include <cuda_bf16.h>
#include <cstdint>

#define BB    8192
#define NVV   778
#define NJJ   16
#define CTOT  2334
#define CPAD  2496          // 13 * 192
#define GK    192           // padded K (145 feat + 1 bias + pad)

// ---------------- device scratch (static; no runtime alloc) ----------------
__device__ __align__(16) float          g_V[(size_t)BB * CPAD];      // GEMM out
__device__ __align__(16) __nv_bfloat16  g_Ahi[BB * GK];
__device__ __align__(16) __nv_bfloat16  g_Alo[BB * GK];
__device__ __align__(16) __nv_bfloat16  g_Bhi[CPAD * GK];            // B^T [n][k]
__device__ __align__(16) __nv_bfloat16  g_Blo[CPAD * GK];
__device__ __align__(16) float g_J0[NJJ * 3];
__device__ __align__(16) float g_JS[NJJ * 3 * 10];
// M'' batch-pair interleaved: [b/2][j][k][parity]  (4096 pairs x 16 j x 12 k x 2)
__device__ __align__(16) float g_M[(BB / 2) * NJJ * 12 * 2];

__constant__ int c_par[16] = {0,0,1,2,0,4,5,0,7,8,0,10,11,0,13,14};
__constant__ int c_inv[16] = {0,5,6,7,9,10,11,17,18,19,13,14,15,1,2,3};

// ---------------- helpers ----------------
__device__ __forceinline__ void split_bf16(float v, __nv_bfloat16& hi,
                                           __nv_bfloat16& lo) {
    hi = __float2bfloat16_rn(v);
    lo = __float2bfloat16_rn(v - __bfloat162float(hi));
}

typedef unsigned long long ull;

__device__ __forceinline__ ull pk2(float lo, float hi) {
    ull r;
    asm("mov.b64 %0, {%1, %2};" : "=l"(r) : "f"(lo), "f"(hi));
    return r;
}
__device__ __forceinline__ void upk2(ull v, float& lo, float& hi) {
    asm("mov.b64 {%0, %1}, %2;" : "=f"(lo), "=f"(hi) : "l"(v));
}
__device__ __forceinline__ ull f2fma(ull a, ull b, ull c) {
    ull d;
    asm("fma.rn.f32x2 %0, %1, %2, %3;" : "=l"(d) : "l"(a), "l"(b), "l"(c));
    return d;
}

__device__ __forceinline__ void mma16816(float* d, const uint32_t* a,
                                         const uint32_t* b) {
    asm volatile(
        "mma.sync.aligned.m16n8k16.row.col.f32.bf16.bf16.f32 "
        "{%0,%1,%2,%3}, {%4,%5,%6,%7}, {%8,%9}, {%0,%1,%2,%3};"
        : "+f"(d[0]), "+f"(d[1]), "+f"(d[2]), "+f"(d[3])
        : "r"(a[0]), "r"(a[1]), "r"(a[2]), "r"(a[3]), "r"(b[0]), "r"(b[1]));
}

// ---------------------------------------------------------------------------
// K0B: build B^T hi/lo [n][k] (n = output column, k = feature)
// ---------------------------------------------------------------------------
__global__ void k0_B(const float* __restrict__ vt,
                     const float* __restrict__ sd,
                     const float* __restrict__ pd) {
    int idx = blockIdx.x * blockDim.x + threadIdx.x;
    if (idx >= CPAD * 24) return;
    int kg = idx % 24;
    int n = idx / 24;

    unsigned short hs[8], ls[8];
#pragma unroll
    for (int i = 0; i < 8; i++) {
        int k = kg * 8 + i;
        float val = 0.f;
        if (n < CTOT) {
            if (k < 10)        val = sd[n * 10 + k];
            else if (k < 145)  val = pd[(k - 10) * CTOT + n];
            else if (k == 145) val = vt[n];
        }
        __nv_bfloat16 hi, lo;
        split_bf16(val, hi, lo);
        hs[i] = __bfloat16_as_ushort(hi);
        ls[i] = __bfloat16_as_ushort(lo);
    }
    uint4 ph, pl;
    ph.x = hs[0] | ((uint32_t)hs[1] << 16); ph.y = hs[2] | ((uint32_t)hs[3] << 16);
    ph.z = hs[4] | ((uint32_t)hs[5] << 16); ph.w = hs[6] | ((uint32_t)hs[7] << 16);
    pl.x = ls[0] | ((uint32_t)ls[1] << 16); pl.y = ls[2] | ((uint32_t)ls[3] << 16);
    pl.z = ls[4] | ((uint32_t)ls[5] << 16); pl.w = ls[6] | ((uint32_t)ls[7] << 16);
    *reinterpret_cast<uint4*>(&g_Bhi[n * GK + kg * 8]) = ph;
    *reinterpret_cast<uint4*>(&g_Blo[n * GK + kg * 8]) = pl;
}

// ---------------------------------------------------------------------------
// K0A: feat hi/lo bf16 [B x 192]: shape(10) | finger - I (135) | 1 | pad 0
// ---------------------------------------------------------------------------
__global__ void k0_A(const float* __restrict__ shape,
                     const float* __restrict__ finger) {
    int idx = blockIdx.x * blockDim.x + threadIdx.x;
    if (idx >= BB * GK) return;
    int b = idx / GK, k = idx - b * GK;
    float val = 0.f;
    if (k < 10) val = shape[b * 10 + k];
    else if (k < 145) {
        int q = k - 10;
        val = finger[b * 135 + q];
        if (((q % 9) & 3) == 0) val -= 1.0f;
    } else if (k == 145) val = 1.0f;
    __nv_bfloat16 hi, lo;
    split_bf16(val, hi, lo);
    g_Ahi[idx] = hi;
    g_Alo[idx] = lo;
}

// ---------------------------------------------------------------------------
// K1: joint regressor contractions
// ---------------------------------------------------------------------------
__global__ void k1_jreg(const float* __restrict__ jreg,
                        const float* __restrict__ vt,
                        const float* __restrict__ sd) {
    __shared__ float red[33 * 128];
    const int j = blockIdx.x, tid = threadIdx.x;
    float acc[33];
#pragma unroll
    for (int o = 0; o < 33; o++) acc[o] = 0.f;
    for (int v = tid; v < NVV; v += 128) {
        float w = jreg[j * NVV + v];
#pragma unroll
        for (int k = 0; k < 3; k++) {
            acc[k] += w * vt[v * 3 + k];
#pragma unroll
            for (int l = 0; l < 10; l++)
                acc[3 + k * 10 + l] += w * sd[(v * 3 + k) * 10 + l];
        }
    }
    for (int o = 0; o < 33; o++) red[o * 128 + tid] = acc[o];
    __syncthreads();
    if (tid < 33) {
        float s = 0.f;
        for (int i = 0; i < 128; i++) s += red[tid * 128 + i];
        if (tid < 3) g_J0[j * 3 + tid] = s;
        else {
            int o = tid - 3;
            int k = o / 10, l = o - k * 10;
            g_JS[(j * 3 + k) * 10 + l] = s;
        }
    }
}

// ---------------------------------------------------------------------------
// K2: per-batch joint chain, M'' (pair-interleaved), 16 regular joints
// ---------------------------------------------------------------------------
__device__ __forceinline__ void mul4(const float* a, float* d) {
    float t[16];
#pragma unroll
    for (int r = 0; r < 4; r++)
#pragma unroll
        for (int c = 0; c < 4; c++)
            t[r * 4 + c] = a[r * 4 + 0] * d[0 + c] + a[r * 4 + 1] * d[4 + c] +
                           a[r * 4 + 2] * d[8 + c] + a[r * 4 + 3] * d[12 + c];
#pragma unroll
    for (int i = 0; i < 16; i++) d[i] = t[i];
}

__global__ void k2_joints(const float* __restrict__ grmt,
                          const float* __restrict__ frmt,
                          const float* __restrict__ shape,
                          const float* __restrict__ trans,
                          float* __restrict__ outJ) {
    __shared__ float sJ[16][3];
    __shared__ float sM[16][16];
    __shared__ float sg[9], st[3], ssh[10];
    const int b = blockIdx.x, tid = threadIdx.x;

    if (tid < 9)  sg[tid]  = grmt[b * 9 + tid];
    if (tid < 3)  st[tid]  = trans[b * 3 + tid];
    if (tid < 10) ssh[tid] = shape[b * 10 + tid];
    __syncthreads();

    if (tid < 48) {
        int j = tid / 3, k = tid - j * 3;
        float a = g_J0[j * 3 + k];
#pragma unroll
        for (int l = 0; l < 10; l++) a += ssh[l] * g_JS[(j * 3 + k) * 10 + l];
        sJ[j][k] = a;
    }
    __syncthreads();

    if (tid < 16) {
        int j = tid;
        float R[9];
        if (j == 0) {
            R[0]=1;R[1]=0;R[2]=0;R[3]=0;R[4]=1;R[5]=0;R[6]=0;R[7]=0;R[8]=1;
        } else {
#pragma unroll
            for (int i = 0; i < 9; i++) R[i] = frmt[b * 135 + (j - 1) * 9 + i];
        }
        float t0 = sJ[j][0], t1 = sJ[j][1], t2 = sJ[j][2];
        if (j > 0) {
            int p = c_par[j];
            t0 -= sJ[p][0]; t1 -= sJ[p][1]; t2 -= sJ[p][2];
        }
        float* m = sM[j];
        m[0]=R[0]; m[1]=R[1]; m[2]=R[2];  m[3]=t0;
        m[4]=R[3]; m[5]=R[4]; m[6]=R[5];  m[7]=t1;
        m[8]=R[6]; m[9]=R[7]; m[10]=R[8]; m[11]=t2;
        m[12]=0.f; m[13]=0.f; m[14]=0.f;  m[15]=1.f;
    }
    __syncthreads();

    if (tid < 5) {
        int j = 1 + 3 * tid;
        mul4(sM[0], sM[j]);
        mul4(sM[j], sM[j + 1]);
        mul4(sM[j + 1], sM[j + 2]);
    }
    __syncthreads();

    if (tid < 16) {
        int j = tid;
        const float* m = sM[j];
        float jt0 = m[3], jt1 = m[7], jt2 = m[11];
        float J0 = sJ[j][0], J1 = sJ[j][1], J2 = sJ[j][2];
        float tc0 = jt0 - (m[0] * J0 + m[1] * J1 + m[2]  * J2);
        float tc1 = jt1 - (m[4] * J0 + m[5] * J1 + m[6]  * J2);
        float tc2 = jt2 - (m[8] * J0 + m[9] * J1 + m[10] * J2);
        // pair-interleaved output
        float* o = &g_M[(((b >> 1) * 16 + j) * 12) * 2 + (b & 1)];
        float row[12];
        int jp = c_inv[j];
#pragma unroll
        for (int r = 0; r < 3; r++) {
            float a = sg[r * 3 + 0], bb = sg[r * 3 + 1], cc = sg[r * 3 + 2];
            row[r * 4 + 0] = a * m[0] + bb * m[4] + cc * m[8];
            row[r * 4 + 1] = a * m[1] + bb * m[5] + cc * m[9];
            row[r * 4 + 2] = a * m[2] + bb * m[6] + cc * m[10];
            row[r * 4 + 3] = a * tc0  + bb * tc1  + cc * tc2 + st[r];
            outJ[(b * 21 + jp) * 3 + r] = a * jt0 + bb * jt1 + cc * jt2 + st[r];
        }
#pragma unroll
        for (int k = 0; k < 12; k++) o[k * 2] = row[k];
    }
}

// ---------------------------------------------------------------------------
// K3: mma.sync bf16-split GEMM. CTA: 512 thr, tile 128(b) x 192(n), K=192
//   smem: Ahi/Alo 128x72 bf16 each, Bhi/Blo 192x72 bf16 each (stride 72)
// ---------------------------------------------------------------------------
#define SA_HI 0
#define SA_LO 18432
#define SB_HI 36864
#define SB_LO 64512
#define SM_K3 92160

__global__ __launch_bounds__(512, 1) void k3_gemm() {
    extern __shared__ __align__(16) char smem[];
    const int tid = threadIdx.x;
    const int wid = tid >> 5, lane = tid & 31;
    const int wm = wid & 1, wn = wid >> 1;      // 2 m-warps x 8 n-warps
    const int gid = lane >> 2, tig = lane & 3;
    const int b0 = blockIdx.x * 128;
    const int t  = blockIdx.y;

    float d[4][3][4];
#pragma unroll
    for (int mt = 0; mt < 4; mt++)
#pragma unroll
        for (int nt = 0; nt < 3; nt++)
#pragma unroll
            for (int q = 0; q < 4; q++) d[mt][nt][q] = 0.f;

    for (int ch = 0; ch < 3; ch++) {
        __syncthreads();
        // stage A hi/lo: 128 rows x 64 k -> 8 uint4/row, 2 splits = 2048 tasks
        for (int i = tid; i < 2048; i += 512) {
            int split = i >> 10, r = (i >> 3) & 127, q = i & 7;
            const __nv_bfloat16* src = split ? g_Alo : g_Ahi;
            uint4 v = *reinterpret_cast<const uint4*>(
                &src[(b0 + r) * GK + ch * 64 + q * 8]);
            *reinterpret_cast<uint4*>(
                smem + (split ? SA_LO : SA_HI) + r * 144 + q * 16) = v;
        }
        // stage B hi/lo: 192 rows x 64 k = 3072 tasks
        for (int i = tid; i < 3072; i += 512) {
            int split = i / 1536, rem = i - split * 1536;
            int r = rem >> 3, q = rem & 7;
            const __nv_bfloat16* src = split ? g_Blo : g_Bhi;
            uint4 v = *reinterpret_cast<const uint4*>(
                &src[(t * 192 + r) * GK + ch * 64 + q * 8]);
            *reinterpret_cast<uint4*>(
                smem + (split ? SB_LO : SB_HI) + r * 144 + q * 16) = v;
        }
        __syncthreads();

#pragma unroll
        for (int ks = 0; ks < 4; ks++) {
            const int kb = ks * 32 + tig * 4;
            uint32_t ah[4][4], al[4][4];
#pragma unroll
            for (int mt = 0; mt < 4; mt++) {
                int r0 = wm * 64 + mt * 16 + gid;
                const char* ph = smem + SA_HI + r0 * 144 + kb;
                const char* pl = smem + SA_LO + r0 * 144 + kb;
                ah[mt][0] = *(const uint32_t*)(ph);
                ah[mt][1] = *(const uint32_t*)(ph + 8 * 144);
                ah[mt][2] = *(const uint32_t*)(ph + 16);
                ah[mt][3] = *(const uint32_t*)(ph + 8 * 144 + 16);
                al[mt][0] = *(const uint32_t*)(pl);
                al[mt][1] = *(const uint32_t*)(pl + 8 * 144);
                al[mt][2] = *(const uint32_t*)(pl + 16);
                al[mt][3] = *(const uint32_t*)(pl + 8 * 144 + 16);
            }
            uint32_t bh[3][2], bl[3][2];
#pragma unroll
            for (int nt = 0; nt < 3; nt++) {
                int n0 = wn * 24 + nt * 8 + gid;
                const char* ph = smem + SB_HI + n0 * 144 + kb;
                const char* pl = smem + SB_LO + n0 * 144 + kb;
                bh[nt][0] = *(const uint32_t*)(ph);
                bh[nt][1] = *(const uint32_t*)(ph + 16);
                bl[nt][0] = *(const uint32_t*)(pl);
                bl[nt][1] = *(const uint32_t*)(pl + 16);
            }
#pragma unroll
            for (int mt = 0; mt < 4; mt++)
#pragma unroll
                for (int nt = 0; nt < 3; nt++) {
                    mma16816(d[mt][nt], ah[mt], bh[nt]);
                    mma16816(d[mt][nt], al[mt], bh[nt]);
                    mma16816(d[mt][nt], ah[mt], bl[nt]);
                }
        }
    }

    // writeout to g_V
#pragma unroll
    for (int mt = 0; mt < 4; mt++) {
        int r0 = b0 + wm * 64 + mt * 16 + gid;
#pragma unroll
        for (int nt = 0; nt < 3; nt++) {
            int c = t * 192 + wn * 24 + nt * 8 + tig * 2;
            *reinterpret_cast<float2*>(&g_V[(size_t)r0 * CPAD + c]) =
                make_float2(d[mt][nt][0], d[mt][nt][1]);
            *reinterpret_cast<float2*>(&g_V[(size_t)(r0 + 8) * CPAD + c]) =
                make_float2(d[mt][nt][2], d[mt][nt][3]);
        }
    }
}

// ---------------------------------------------------------------------------
// K4: LBS epilogue, f32x2-packed over batch pairs.
//   CTA: 256 thr, tile 32 batch x 64 verts. thread = (bq pair, 4 verts)
// ---------------------------------------------------------------------------
__global__ __launch_bounds__(256, 2) void k4_epi(const float* __restrict__ lbs,
                                                 float* __restrict__ outV,
                                                 float* __restrict__ outJ) {
    __shared__ __align__(16) float sMmP[16 * 392];   // [pair][j*24 + k*2 + par]
    __shared__ __align__(16) float sW2[16 * 64 * 2]; // [j][v][dup]
    const int tid = threadIdx.x;
    const int b0 = blockIdx.x * 32;
    const int v0 = blockIdx.y * 64;
    const int c0 = v0 * 3;

    // stage M'' pairs: 16 pairs x 384 floats (contiguous src)
    {
        const float4* src = reinterpret_cast<const float4*>(
            &g_M[(size_t)(b0 / 2) * 384]);
        for (int i = tid; i < 1536; i += 256) {
            int pr = i / 96, q = i - pr * 96;
            *reinterpret_cast<float4*>(&sMmP[pr * 392 + q * 4]) = src[i];
        }
    }
    // stage duplicated weights
    for (int i = tid; i < 1024; i += 256) {
        int v = i >> 4, j = i & 15;
        float w = (v0 + v < NVV) ? lbs[(v0 + v) * 16 + j] : 0.f;
        sW2[(j * 64 + v) * 2]     = w;
        sW2[(j * 64 + v) * 2 + 1] = w;
    }
    __syncthreads();

    const int vq = tid & 15;
    const int bq = tid >> 4;
    const int bA = b0 + bq * 2;       // even batch of the pair

    // load V for both batches (coalesced: 12 consecutive floats each)
    float va[12], vb[12];
    {
        const float* p0 = &g_V[(size_t)bA * CPAD + c0 + vq * 12];
        const float* p1 = p0 + CPAD;
#pragma unroll
        for (int q = 0; q < 3; q++) {
            float4 x0 = reinterpret_cast<const float4*>(p0)[q];
            float4 x1 = reinterpret_cast<const float4*>(p1)[q];
            va[q*4+0]=x0.x; va[q*4+1]=x0.y; va[q*4+2]=x0.z; va[q*4+3]=x0.w;
            vb[q*4+0]=x1.x; vb[q*4+1]=x1.y; vb[q*4+2]=x1.z; vb[q*4+3]=x1.w;
        }
    }
    ull pX[4], pY[4], pZ[4];
#pragma unroll
    for (int vi = 0; vi < 4; vi++) {
        pX[vi] = pk2(va[vi * 3 + 0], vb[vi * 3 + 0]);
        pY[vi] = pk2(va[vi * 3 + 1], vb[vi * 3 + 1]);
        pZ[vi] = pk2(va[vi * 3 + 2], vb[vi * 3 + 2]);
    }

    ull o[12];
#pragma unroll
    for (int i = 0; i < 12; i++) o[i] = 0ull;

#pragma unroll 4
    for (int j = 0; j < 16; j++) {
        const ull* mp = reinterpret_cast<const ull*>(&sMmP[bq * 392 + j * 24]);
        const ull* wp = reinterpret_cast<const ull*>(&sW2[(j * 64 + vq * 4) * 2]);
        ull m0 = mp[0], m1 = mp[1], m2 = mp[2],  m3 = mp[3];
        ull m4 = mp[4], m5 = mp[5], m6 = mp[6],  m7 = mp[7];
        ull m8 = mp[8], m9 = mp[9], m10 = mp[10], m11 = mp[11];
#pragma unroll
        for (int vi = 0; vi < 4; vi++) {
            ull w = wp[vi];
            ull t0 = f2fma(m0, pX[vi], f2fma(m1, pY[vi], f2fma(m2,  pZ[vi], m3)));
            ull t1 = f2fma(m4, pX[vi], f2fma(m5, pY[vi], f2fma(m6,  pZ[vi], m7)));
            ull t2 = f2fma(m8, pX[vi], f2fma(m9, pY[vi], f2fma(m10, pZ[vi], m11)));
            o[vi * 3 + 0] = f2fma(w, t0, o[vi * 3 + 0]);
            o[vi * 3 + 1] = f2fma(w, t1, o[vi * 3 + 1]);
            o[vi * 3 + 2] = f2fma(w, t2, o[vi * 3 + 2]);
        }
    }

    // unpack
    float oa[12], ob[12];
#pragma unroll
    for (int i = 0; i < 12; i++) upk2(o[i], oa[i], ob[i]);

    // fingertip joints
#pragma unroll
    for (int vi = 0; vi < 4; vi++) {
        int v = v0 + vq * 4 + vi;
        int tp = -1;
        if (v == 745) tp = 4; else if (v == 317) tp = 8;
        else if (v == 444) tp = 12; else if (v == 556) tp = 16;
        else if (v == 673) tp = 20;
        if (tp >= 0) {
            int base = vi * 3;
            outJ[((bA)     * 21 + tp) * 3 + 0] = oa[base + 0];
            outJ[((bA)     * 21 + tp) * 3 + 1] = oa[base + 1];
            outJ[((bA)     * 21 + tp) * 3 + 2] = oa[base + 2];
            outJ[((bA + 1) * 21 + tp) * 3 + 0] = ob[base + 0];
            outJ[((bA + 1) * 21 + tp) * 3 + 1] = ob[base + 1];
            outJ[((bA + 1) * 21 + tp) * 3 + 2] = ob[base + 2];
        }
    }

    // writeout (12 consecutive floats per batch, float2 stores)
    const int cbase = c0 + vq * 12;
    if (cbase + 12 <= CTOT) {
        float* p0 = &outV[(size_t)bA * CTOT + cbase];
        float* p1 = p0 + CTOT;
#pragma unroll
        for (int q = 0; q < 6; q++) {
            reinterpret_cast<float2*>(p0)[q] = make_float2(oa[q*2], oa[q*2+1]);
            reinterpret_cast<float2*>(p1)[q] = make_float2(ob[q*2], ob[q*2+1]);
        }
    } else if (cbase < CTOT) {
        int nval = CTOT - cbase;
        float* p0 = &outV[(size_t)bA * CTOT + cbase];
        float* p1 = p0 + CTOT;
        for (int q = 0; q < nval; q++) { p0[q] = oa[q]; p1[q] = ob[q]; }
    }
}

// ---------------------------------------------------------------------------
extern "C" void kernel_launch(void* const* d_in, const int* in_sizes, int n_in,
                              void* d_out, int out_size) {
    const float* grmt  = (const float*)d_in[0];
    const float* frmt  = (const float*)d_in[1];
    const float* shape = (const float*)d_in[2];
    const float* trans = (const float*)d_in[3];
    const float* vt    = (const float*)d_in[4];
    const float* sd    = (const float*)d_in[5];
    const float* jreg  = (const float*)d_in[6];
    const float* pd    = (const float*)d_in[7];
    const float* lbs   = (const float*)d_in[8];

    float* out  = (float*)d_out;
    float* outV = out;
    float* outJ = out + (size_t)BB * CTOT;

    static bool attr_done = false;
    if (!attr_done) {
        cudaFuncSetAttribute(k3_gemm, cudaFuncAttributeMaxDynamicSharedMemorySize,
                             SM_K3);
        attr_done = true;
    }

    k0_B<<<(CPAD * 24 + 255) / 256, 256>>>(vt, sd, pd);
    k0_A<<<(BB * GK) / 256, 256>>>(shape, frmt);
    k1_jreg<<<NJJ, 128>>>(jreg, vt, sd);
    k2_joints<<<BB, 64>>>(grmt, frmt, shape, trans, outJ);
    k3_gemm<<<dim3(BB / 128, 13), 512, SM_K3>>>();
    k4_epi<<<dim3(BB / 32, 13), 256>>>(lbs, outV, outJ);
}